// round 15
// baseline (speedup 1.0000x reference)
#include <cuda_runtime.h>

#define NIMG_MAX 64
#define HH 1024
#define WW 1024
#define NB 131072         // 256 * 512 bins per image
#define EBLK 16           // entropy partial blocks per image
#define TH 16             // rows per stripe (4096 blocks: finest balance unit)
#define NSTRIPE (HH / TH)

// 32 MB histogram scratch (zeroed by a graph memset node each invocation).
// Phase discipline (hard-won): memset writes it, k_hist REDs it, k_entropy
// reads it — never concurrently (concurrent read poisons the LTS atomic pipe).
__device__ __align__(16) int   g_hist[NIMG_MAX * NB];
__device__ __align__(16) float g_partial[NIMG_MAX * EBLK];
__device__ unsigned int g_done;   // zero-init; reset by last entropy block

// ---------------------------------------------------------------- histogram
// Register-resident sliding window, 4-row software pipeline.
// Halo columns via warp SHFL; lanes 0/31 use a 1-sector predicated LDG.

struct Row6 { int v0, v1, v2, v3, vl, vr; };

__device__ __forceinline__ Row6 load_row(const float* __restrict__ p, bool valid,
                                         int lane, bool lv, bool rv) {
    Row6 r;
    float e = 0.0f;
    if (valid) {
        if (lane == 0  && lv) e = __ldg(p - 1);
        if (lane == 31 && rv) e = __ldg(p + 4);
        float4 f = *(const float4*)p;
        r.v0 = (int)(f.x * 255.0f);
        r.v1 = (int)(f.y * 255.0f);
        r.v2 = (int)(f.z * 255.0f);
        r.v3 = (int)(f.w * 255.0f);
    } else {
        r.v0 = r.v1 = r.v2 = r.v3 = 0;
    }
    int ei = (int)(e * 255.0f);
    int up = __shfl_up_sync(0xffffffffu, r.v3, 1);
    int dn = __shfl_down_sync(0xffffffffu, r.v0, 1);
    r.vl = (lane == 0)  ? (valid && lv ? ei : 0) : up;
    r.vr = (lane == 31) ? (valid && rv ? ei : 0) : dn;
    if (!valid) { r.vl = 0; r.vr = 0; }
    return r;
}

template<bool SPEC>
__device__ __forceinline__ void hist_body(const float* __restrict__ p, int ry0,
                                          int* __restrict__ hist,
                                          int lane, bool lv, bool rv) {
    Row6 t = load_row(p, ry0 > 0, lane, lv, rv);         p += WW;
    Row6 m = load_row(p, true, lane, lv, rv);            p += WW;

    int st0 = t.vl + t.v0 + t.v1, st1 = t.v0 + t.v1 + t.v2;
    int st2 = t.v1 + t.v2 + t.v3, st3 = t.v2 + t.v3 + t.vr;
    int sm0 = m.vl + m.v1, sm1 = m.v0 + m.v2;
    int sm2 = m.v1 + m.v3, sm3 = m.v2 + m.vr;
    int c0 = m.v0, c1 = m.v1, c2 = m.v2, c3 = m.v3;

    #pragma unroll 1
    for (int rb = 0; rb < TH; rb += 4) {
        // front-load 4 rows: 4 independent LDG.128 in flight before any use
        Row6 b[4];
        #pragma unroll
        for (int j = 0; j < 4; ++j)
            b[j] = load_row(p + j * WW, ry0 + rb + j + 1 < HH, lane, lv, rv);
        p += 4 * WW;

        #pragma unroll
        for (int j = 0; j < 4; ++j) {
            int sb0 = b[j].vl + b[j].v0 + b[j].v1;
            int sb1 = b[j].v0 + b[j].v1 + b[j].v2;
            int sb2 = b[j].v1 + b[j].v2 + b[j].v3;
            int sb3 = b[j].v2 + b[j].v3 + b[j].vr;

            int n0 = st0 + sm0 + sb0;
            int n1 = st1 + sm1 + sb1;
            int n2 = st2 + sm2 + sb2;
            int n3 = st3 + sm3 + sb3;

            // (nb*13108)>>16 == trunc(nb/5); 21846 -> trunc(nb/3)
            int mul = 13108;
            if (SPEC) {
                int gr = ry0 + rb + j;
                mul = (gr == 0 || gr == HH - 1) ? 21846 : 13108;
            }
            atomicAdd(&hist[(c0 << 9) + ((n0 * mul) >> 16)], 1);
            atomicAdd(&hist[(c1 << 9) + ((n1 * mul) >> 16)], 1);
            atomicAdd(&hist[(c2 << 9) + ((n2 * mul) >> 16)], 1);
            atomicAdd(&hist[(c3 << 9) + ((n3 * mul) >> 16)], 1);

            st0 = sm0 + c0; st1 = sm1 + c1; st2 = sm2 + c2; st3 = sm3 + c3;
            sm0 = sb0 - b[j].v0; sm1 = sb1 - b[j].v1;
            sm2 = sb2 - b[j].v2; sm3 = sb3 - b[j].v3;
            c0 = b[j].v0; c1 = b[j].v1; c2 = b[j].v2; c3 = b[j].v3;
        }
    }
}

__global__ __launch_bounds__(256) void k_hist(const float* __restrict__ x, int B) {
    const int img = blockIdx.z;
    const int ry0 = blockIdx.y * TH;
    const int c    = threadIdx.x * 4;           // 256 threads * 4 = 1024 cols
    const int lane = threadIdx.x & 31;
    const bool lv = (c > 0);
    const bool rv = (c + 4 < WW);

    const float* p = x + (size_t)img * (HH * (size_t)WW) + (size_t)(ry0 - 1) * WW + c;
    int* hist = g_hist + img * NB;

    const bool spec = (img == 0 || img == B - 1) &&
                      (blockIdx.y == 0 || blockIdx.y == NSTRIPE - 1);
    if (spec) hist_body<true >(p, ry0, hist, lane, lv, rv);
    else      hist_body<false>(p, ry0, hist, lane, lv, rv);
}

// ---------------------------------------------------------------- entropy (+ final)
// Read-only over the histogram (measured-best form: branch + MUFU).
__global__ __launch_bounds__(256) void k_entropy(float* __restrict__ out, int B) {
    const int img = blockIdx.y;
    const int4* h = (const int4*)(g_hist + img * NB);
    const int n4 = NB / 4;

    float acc = 0.0f;
    for (int i = blockIdx.x * blockDim.x + threadIdx.x; i < n4;
         i += gridDim.x * blockDim.x) {
        int4 v = h[i];
        if (v.x) acc += (float)v.x * __log2f((float)v.x);
        if (v.y) acc += (float)v.y * __log2f((float)v.y);
        if (v.z) acc += (float)v.z * __log2f((float)v.z);
        if (v.w) acc += (float)v.w * __log2f((float)v.w);
    }

    __shared__ float sm[256];
    __shared__ bool last;
    sm[threadIdx.x] = acc;
    __syncthreads();
    for (int s = 128; s > 0; s >>= 1) {
        if (threadIdx.x < s) sm[threadIdx.x] += sm[threadIdx.x + s];
        __syncthreads();
    }
    if (threadIdx.x == 0) {
        g_partial[img * EBLK + blockIdx.x] = sm[0];   // fixed slot: deterministic
        __threadfence();
        unsigned v = atomicAdd(&g_done, 1u);
        last = (v == gridDim.x * gridDim.y - 1);
    }
    __syncthreads();

    if (last) {
        const int t = threadIdx.x;
        float e = 0.0f;
        if (t < B) {
            float s = 0.0f;
            #pragma unroll
            for (int j = 0; j < EBLK; ++j) s += g_partial[t * EBLK + j];
            e = 20.0f - s * (1.0f / 1048576.0f);   // log2(2^20) - sum/2^20
        }
        __syncthreads();
        sm[t] = (t < 64) ? e : 0.0f;
        __syncthreads();
        for (int s = 32; s > 0; s >>= 1) {
            if (t < s) sm[t] += sm[t + s];
            __syncthreads();
        }
        if (t == 0) {
            out[0] = sm[0] / (float)B;
            g_done = 0;                 // reset for next graph replay
        }
    }
}

// ---------------------------------------------------------------- launch
extern "C" void kernel_launch(void* const* d_in, const int* in_sizes, int n_in,
                              void* d_out, int out_size) {
    const float* x = (const float*)d_in[0];
    int B = in_sizes[0] / (HH * WW);
    if (B > NIMG_MAX) B = NIMG_MAX;

    // bulk zero of the used histogram range: captured as a graph memset node
    void* hp = nullptr;
    cudaGetSymbolAddress(&hp, g_hist);
    cudaMemsetAsync(hp, 0, (size_t)B * NB * sizeof(int));

    dim3 gh(1, NSTRIPE, B);          // 1 x 64 x 64 = 4096 blocks
    k_hist<<<gh, 256>>>(x, B);

    k_entropy<<<dim3(EBLK, B), 256>>>((float*)d_out, B);
}

// round 16
// speedup vs baseline: 1.0068x; 1.0068x over previous
#include <cuda_runtime.h>

#define NIMG_MAX 64
#define HH 1024
#define WW 1024
#define NB 131072         // 256 * 512 bins per image
#define EBLK 16           // entropy partial blocks per image
#define TH 32             // rows per stripe (2048 blocks: measured optimum)
#define NSTRIPE (HH / TH)

// 32 MB histogram scratch (zeroed by a graph memset node each invocation).
// Phase discipline (hard-won): memset writes it, k_hist REDs it, k_entropy
// reads it — never concurrently (concurrent read poisons the LTS atomic pipe).
__device__ __align__(16) int   g_hist[NIMG_MAX * NB];
__device__ __align__(16) float g_partial[NIMG_MAX * EBLK];
__device__ unsigned int g_done;   // zero-init; reset by last entropy block

// ---------------------------------------------------------------- histogram
// Register-resident sliding window, 4-row software pipeline.
// Halo columns via warp SHFL; lanes 0/31 use a 1-sector predicated LDG.
// All input loads are __ldcs (evict-first) so the histogram stays L2-resident.

struct Row6 { int v0, v1, v2, v3, vl, vr; };

__device__ __forceinline__ Row6 load_row(const float* __restrict__ p, bool valid,
                                         int lane, bool lv, bool rv) {
    Row6 r;
    float e = 0.0f;
    if (valid) {
        if (lane == 0  && lv) e = __ldcs(p - 1);
        if (lane == 31 && rv) e = __ldcs(p + 4);
        float4 f = __ldcs((const float4*)p);
        r.v0 = (int)(f.x * 255.0f);
        r.v1 = (int)(f.y * 255.0f);
        r.v2 = (int)(f.z * 255.0f);
        r.v3 = (int)(f.w * 255.0f);
    } else {
        r.v0 = r.v1 = r.v2 = r.v3 = 0;
    }
    int ei = (int)(e * 255.0f);
    int up = __shfl_up_sync(0xffffffffu, r.v3, 1);
    int dn = __shfl_down_sync(0xffffffffu, r.v0, 1);
    r.vl = (lane == 0)  ? (valid && lv ? ei : 0) : up;
    r.vr = (lane == 31) ? (valid && rv ? ei : 0) : dn;
    if (!valid) { r.vl = 0; r.vr = 0; }
    return r;
}

template<bool SPEC>
__device__ __forceinline__ void hist_body(const float* __restrict__ p, int ry0,
                                          int* __restrict__ hist,
                                          int lane, bool lv, bool rv) {
    Row6 t = load_row(p, ry0 > 0, lane, lv, rv);         p += WW;
    Row6 m = load_row(p, true, lane, lv, rv);            p += WW;

    int st0 = t.vl + t.v0 + t.v1, st1 = t.v0 + t.v1 + t.v2;
    int st2 = t.v1 + t.v2 + t.v3, st3 = t.v2 + t.v3 + t.vr;
    int sm0 = m.vl + m.v1, sm1 = m.v0 + m.v2;
    int sm2 = m.v1 + m.v3, sm3 = m.v2 + m.vr;
    int c0 = m.v0, c1 = m.v1, c2 = m.v2, c3 = m.v3;

    #pragma unroll 1
    for (int rb = 0; rb < TH; rb += 4) {
        // front-load 4 rows: 4 independent LDG.128 in flight before any use
        Row6 b[4];
        #pragma unroll
        for (int j = 0; j < 4; ++j)
            b[j] = load_row(p + j * WW, ry0 + rb + j + 1 < HH, lane, lv, rv);
        p += 4 * WW;

        #pragma unroll
        for (int j = 0; j < 4; ++j) {
            int sb0 = b[j].vl + b[j].v0 + b[j].v1;
            int sb1 = b[j].v0 + b[j].v1 + b[j].v2;
            int sb2 = b[j].v1 + b[j].v2 + b[j].v3;
            int sb3 = b[j].v2 + b[j].v3 + b[j].vr;

            int n0 = st0 + sm0 + sb0;
            int n1 = st1 + sm1 + sb1;
            int n2 = st2 + sm2 + sb2;
            int n3 = st3 + sm3 + sb3;

            // (nb*13108)>>16 == trunc(nb/5); 21846 -> trunc(nb/3)
            int mul = 13108;
            if (SPEC) {
                int gr = ry0 + rb + j;
                mul = (gr == 0 || gr == HH - 1) ? 21846 : 13108;
            }
            atomicAdd(&hist[(c0 << 9) + ((n0 * mul) >> 16)], 1);
            atomicAdd(&hist[(c1 << 9) + ((n1 * mul) >> 16)], 1);
            atomicAdd(&hist[(c2 << 9) + ((n2 * mul) >> 16)], 1);
            atomicAdd(&hist[(c3 << 9) + ((n3 * mul) >> 16)], 1);

            st0 = sm0 + c0; st1 = sm1 + c1; st2 = sm2 + c2; st3 = sm3 + c3;
            sm0 = sb0 - b[j].v0; sm1 = sb1 - b[j].v1;
            sm2 = sb2 - b[j].v2; sm3 = sb3 - b[j].v3;
            c0 = b[j].v0; c1 = b[j].v1; c2 = b[j].v2; c3 = b[j].v3;
        }
    }
}

__global__ __launch_bounds__(256) void k_hist(const float* __restrict__ x, int B) {
    const int img = blockIdx.z;
    const int ry0 = blockIdx.y * TH;
    const int c    = threadIdx.x * 4;           // 256 threads * 4 = 1024 cols
    const int lane = threadIdx.x & 31;
    const bool lv = (c > 0);
    const bool rv = (c + 4 < WW);

    const float* p = x + (size_t)img * (HH * (size_t)WW) + (size_t)(ry0 - 1) * WW + c;
    int* hist = g_hist + img * NB;

    const bool spec = (img == 0 || img == B - 1) &&
                      (blockIdx.y == 0 || blockIdx.y == NSTRIPE - 1);
    if (spec) hist_body<true >(p, ry0, hist, lane, lv, rv);
    else      hist_body<false>(p, ry0, hist, lane, lv, rv);
}

// ---------------------------------------------------------------- entropy (+ final)
// Read-only over the histogram (measured-best form: branch + MUFU).
__global__ __launch_bounds__(256) void k_entropy(float* __restrict__ out, int B) {
    const int img = blockIdx.y;
    const int4* h = (const int4*)(g_hist + img * NB);
    const int n4 = NB / 4;

    float acc = 0.0f;
    for (int i = blockIdx.x * blockDim.x + threadIdx.x; i < n4;
         i += gridDim.x * blockDim.x) {
        int4 v = h[i];
        if (v.x) acc += (float)v.x * __log2f((float)v.x);
        if (v.y) acc += (float)v.y * __log2f((float)v.y);
        if (v.z) acc += (float)v.z * __log2f((float)v.z);
        if (v.w) acc += (float)v.w * __log2f((float)v.w);
    }

    __shared__ float sm[256];
    __shared__ bool last;
    sm[threadIdx.x] = acc;
    __syncthreads();
    for (int s = 128; s > 0; s >>= 1) {
        if (threadIdx.x < s) sm[threadIdx.x] += sm[threadIdx.x + s];
        __syncthreads();
    }
    if (threadIdx.x == 0) {
        g_partial[img * EBLK + blockIdx.x] = sm[0];   // fixed slot: deterministic
        __threadfence();
        unsigned v = atomicAdd(&g_done, 1u);
        last = (v == gridDim.x * gridDim.y - 1);
    }
    __syncthreads();

    if (last) {
        const int t = threadIdx.x;
        float e = 0.0f;
        if (t < B) {
            float s = 0.0f;
            #pragma unroll
            for (int j = 0; j < EBLK; ++j) s += g_partial[t * EBLK + j];
            e = 20.0f - s * (1.0f / 1048576.0f);   // log2(2^20) - sum/2^20
        }
        __syncthreads();
        sm[t] = (t < 64) ? e : 0.0f;
        __syncthreads();
        for (int s = 32; s > 0; s >>= 1) {
            if (t < s) sm[t] += sm[t + s];
            __syncthreads();
        }
        if (t == 0) {
            out[0] = sm[0] / (float)B;
            g_done = 0;                 // reset for next graph replay
        }
    }
}

// ---------------------------------------------------------------- launch
extern "C" void kernel_launch(void* const* d_in, const int* in_sizes, int n_in,
                              void* d_out, int out_size) {
    const float* x = (const float*)d_in[0];
    int B = in_sizes[0] / (HH * WW);
    if (B > NIMG_MAX) B = NIMG_MAX;

    // bulk zero of the used histogram range: captured as a graph memset node
    void* hp = nullptr;
    cudaGetSymbolAddress(&hp, g_hist);
    cudaMemsetAsync(hp, 0, (size_t)B * NB * sizeof(int));

    dim3 gh(1, NSTRIPE, B);          // 1 x 32 x 64 = 2048 blocks
    k_hist<<<gh, 256>>>(x, B);

    k_entropy<<<dim3(EBLK, B), 256>>>((float*)d_out, B);
}

// round 17
// speedup vs baseline: 1.0116x; 1.0048x over previous
#include <cuda_runtime.h>

#define NIMG_MAX 64
#define HH 1024
#define WW 1024
#define NB 131072         // 256 * 512 bins per image
#define EBLK 16           // entropy blocks per image (16 q-rows each)
#define TH 32             // rows per stripe (2048 blocks: measured optimum)
#define NSTRIPE (HH / TH)
#define MI4 108           // int4 per q-row scanned: mi < 432 (max mean_i = 425)

// 32 MB histogram scratch (zeroed by a graph memset node each invocation).
// Phase discipline (hard-won): memset writes it, k_hist REDs it, k_entropy
// reads it — never concurrently (concurrent read poisons the LTS atomic pipe).
__device__ __align__(16) int   g_hist[NIMG_MAX * NB];
__device__ __align__(16) float g_partial[NIMG_MAX * EBLK];
__device__ unsigned int g_done;   // zero-init; reset by last entropy block

// ---------------------------------------------------------------- histogram
// Register-resident sliding window, 4-row software pipeline.
// Halo columns via warp SHFL; lanes 0/31 use a 1-sector predicated LDG.

struct Row6 { int v0, v1, v2, v3, vl, vr; };

__device__ __forceinline__ Row6 load_row(const float* __restrict__ p, bool valid,
                                         int lane, bool lv, bool rv) {
    Row6 r;
    float e = 0.0f;
    if (valid) {
        if (lane == 0  && lv) e = __ldg(p - 1);
        if (lane == 31 && rv) e = __ldg(p + 4);
        float4 f = *(const float4*)p;
        r.v0 = (int)(f.x * 255.0f);
        r.v1 = (int)(f.y * 255.0f);
        r.v2 = (int)(f.z * 255.0f);
        r.v3 = (int)(f.w * 255.0f);
    } else {
        r.v0 = r.v1 = r.v2 = r.v3 = 0;
    }
    int ei = (int)(e * 255.0f);
    int up = __shfl_up_sync(0xffffffffu, r.v3, 1);
    int dn = __shfl_down_sync(0xffffffffu, r.v0, 1);
    r.vl = (lane == 0)  ? (valid && lv ? ei : 0) : up;
    r.vr = (lane == 31) ? (valid && rv ? ei : 0) : dn;
    if (!valid) { r.vl = 0; r.vr = 0; }
    return r;
}

template<bool SPEC>
__device__ __forceinline__ void hist_body(const float* __restrict__ p, int ry0,
                                          int* __restrict__ hist,
                                          int lane, bool lv, bool rv) {
    Row6 t = load_row(p, ry0 > 0, lane, lv, rv);         p += WW;
    Row6 m = load_row(p, true, lane, lv, rv);            p += WW;

    int st0 = t.vl + t.v0 + t.v1, st1 = t.v0 + t.v1 + t.v2;
    int st2 = t.v1 + t.v2 + t.v3, st3 = t.v2 + t.v3 + t.vr;
    int sm0 = m.vl + m.v1, sm1 = m.v0 + m.v2;
    int sm2 = m.v1 + m.v3, sm3 = m.v2 + m.vr;
    int c0 = m.v0, c1 = m.v1, c2 = m.v2, c3 = m.v3;

    #pragma unroll 1
    for (int rb = 0; rb < TH; rb += 4) {
        // front-load 4 rows: 4 independent LDG.128 in flight before any use
        Row6 b[4];
        #pragma unroll
        for (int j = 0; j < 4; ++j)
            b[j] = load_row(p + j * WW, ry0 + rb + j + 1 < HH, lane, lv, rv);
        p += 4 * WW;

        #pragma unroll
        for (int j = 0; j < 4; ++j) {
            int sb0 = b[j].vl + b[j].v0 + b[j].v1;
            int sb1 = b[j].v0 + b[j].v1 + b[j].v2;
            int sb2 = b[j].v1 + b[j].v2 + b[j].v3;
            int sb3 = b[j].v2 + b[j].v3 + b[j].vr;

            int n0 = st0 + sm0 + sb0;
            int n1 = st1 + sm1 + sb1;
            int n2 = st2 + sm2 + sb2;
            int n3 = st3 + sm3 + sb3;

            // (nb*13108)>>16 == trunc(nb/5); 21846 -> trunc(nb/3)
            int mul = 13108;
            if (SPEC) {
                int gr = ry0 + rb + j;
                mul = (gr == 0 || gr == HH - 1) ? 21846 : 13108;
            }
            atomicAdd(&hist[(c0 << 9) + ((n0 * mul) >> 16)], 1);
            atomicAdd(&hist[(c1 << 9) + ((n1 * mul) >> 16)], 1);
            atomicAdd(&hist[(c2 << 9) + ((n2 * mul) >> 16)], 1);
            atomicAdd(&hist[(c3 << 9) + ((n3 * mul) >> 16)], 1);

            st0 = sm0 + c0; st1 = sm1 + c1; st2 = sm2 + c2; st3 = sm3 + c3;
            sm0 = sb0 - b[j].v0; sm1 = sb1 - b[j].v1;
            sm2 = sb2 - b[j].v2; sm3 = sb3 - b[j].v3;
            c0 = b[j].v0; c1 = b[j].v1; c2 = b[j].v2; c3 = b[j].v3;
        }
    }
}

__global__ __launch_bounds__(256) void k_hist(const float* __restrict__ x, int B) {
    const int img = blockIdx.z;
    const int ry0 = blockIdx.y * TH;
    const int c    = threadIdx.x * 4;           // 256 threads * 4 = 1024 cols
    const int lane = threadIdx.x & 31;
    const bool lv = (c > 0);
    const bool rv = (c + 4 < WW);

    const float* p = x + (size_t)img * (HH * (size_t)WW) + (size_t)(ry0 - 1) * WW + c;
    int* hist = g_hist + img * NB;

    const bool spec = (img == 0 || img == B - 1) &&
                      (blockIdx.y == 0 || blockIdx.y == NSTRIPE - 1);
    if (spec) hist_body<true >(p, ry0, hist, lane, lv, rv);
    else      hist_body<false>(p, ry0, hist, lane, lv, rv);
}

// ---------------------------------------------------------------- entropy (+ final)
// Read-only over the histogram. Scans only mi < 432 per q-row: mean_i is
// provably <= 425 (interior: 8*255/5=408; divisor-3 rows are edge rows:
// 5*255/3=425), so bins beyond are always zero and never read.
__global__ __launch_bounds__(256) void k_entropy(float* __restrict__ out, int B) {
    const int img = blockIdx.y;
    const int q0  = blockIdx.x * 16;            // 16 q-rows per block
    const int4* h = (const int4*)(g_hist + img * NB);
    const int n = 16 * MI4;                     // 1728 int4 per block

    float acc = 0.0f;
    for (int i = threadIdx.x; i < n; i += 256) {
        int q = (i * 607) >> 16;                // exact i/108 for i < 1728
        int j = i - q * MI4;
        int4 v = h[(q0 + q) * 128 + j];
        if (v.x) acc += (float)v.x * __log2f((float)v.x);
        if (v.y) acc += (float)v.y * __log2f((float)v.y);
        if (v.z) acc += (float)v.z * __log2f((float)v.z);
        if (v.w) acc += (float)v.w * __log2f((float)v.w);
    }

    __shared__ float sm[256];
    __shared__ bool last;
    sm[threadIdx.x] = acc;
    __syncthreads();
    for (int s = 128; s > 0; s >>= 1) {
        if (threadIdx.x < s) sm[threadIdx.x] += sm[threadIdx.x + s];
        __syncthreads();
    }
    if (threadIdx.x == 0) {
        g_partial[img * EBLK + blockIdx.x] = sm[0];   // fixed slot: deterministic
        __threadfence();
        unsigned v = atomicAdd(&g_done, 1u);
        last = (v == gridDim.x * gridDim.y - 1);
    }
    __syncthreads();

    if (last) {
        const int t = threadIdx.x;
        float e = 0.0f;
        if (t < B) {
            float s = 0.0f;
            #pragma unroll
            for (int j = 0; j < EBLK; ++j) s += g_partial[t * EBLK + j];
            e = 20.0f - s * (1.0f / 1048576.0f);   // log2(2^20) - sum/2^20
        }
        __syncthreads();
        sm[t] = (t < 64) ? e : 0.0f;
        __syncthreads();
        for (int s = 32; s > 0; s >>= 1) {
            if (t < s) sm[t] += sm[t + s];
            __syncthreads();
        }
        if (t == 0) {
            out[0] = sm[0] / (float)B;
            g_done = 0;                 // reset for next graph replay
        }
    }
}

// ---------------------------------------------------------------- launch
extern "C" void kernel_launch(void* const* d_in, const int* in_sizes, int n_in,
                              void* d_out, int out_size) {
    const float* x = (const float*)d_in[0];
    int B = in_sizes[0] / (HH * WW);
    if (B > NIMG_MAX) B = NIMG_MAX;

    // bulk zero of the used histogram range: captured as a graph memset node
    void* hp = nullptr;
    cudaGetSymbolAddress(&hp, g_hist);
    cudaMemsetAsync(hp, 0, (size_t)B * NB * sizeof(int));

    dim3 gh(1, NSTRIPE, B);          // 1 x 32 x 64 = 2048 blocks
    k_hist<<<gh, 256>>>(x, B);

    k_entropy<<<dim3(EBLK, B), 256>>>((float*)d_out, B);
}